// round 14
// baseline (speedup 1.0000x reference)
#include <cuda_runtime.h>
#include <cuda_fp16.h>
#include <cstdint>

#define N_NODES 50000
#define E_MAX   800000
#define DH 256
#define DOUT 64
#define SLOPE 0.01f

// ---------------------------------------------------------------------------
// Scratch (allocation-free rule: __device__ globals)
// ---------------------------------------------------------------------------
__device__ __half g_h[(size_t)N_NODES * DH];  // GEMM output per layer (fp16)
__device__ int    g_deg[N_NODES];
__device__ float  g_dinv[N_NODES];
__device__ int    g_row_off[N_NODES + 1];
__device__ int    g_cursor[N_NODES];
__device__ int    g_csr_src[E_MAX];
__device__ int    g_pub[256];                 // lookback scan: (sum<<2)|flag

__device__ __forceinline__ uint32_t smem_to_u32(const void* p) {
    uint32_t a;
    asm("{ .reg .u64 t; cvta.to.shared.u64 t, %1; cvt.u32.u64 %0, t; }" : "=r"(a) : "l"(p));
    return a;
}
__device__ __forceinline__ uint32_t f2tf32(float f) {
    uint32_t o;
    asm("cvt.rna.tf32.f32 %0, %1;" : "=r"(o) : "f"(f));
    return o;
}

#define LDSM_X4(R, ADDR) \
    asm volatile("ldmatrix.sync.aligned.m8n8.x4.shared.b16 {%0,%1,%2,%3}, [%4];" \
                 : "=r"((R)[0]), "=r"((R)[1]), "=r"((R)[2]), "=r"((R)[3]) : "r"(ADDR))

#define MMA_TF32(C, A, B0, B1) \
    asm volatile("mma.sync.aligned.m16n8k8.row.col.f32.tf32.tf32.f32 " \
                 "{%0,%1,%2,%3}, {%4,%5,%6,%7}, {%8,%9}, {%0,%1,%2,%3};" \
                 : "+f"((C)[0]), "+f"((C)[1]), "+f"((C)[2]), "+f"((C)[3]) \
                 : "r"((A)[0]), "r"((A)[1]), "r"((A)[2]), "r"((A)[3]), "r"(B0), "r"(B1))

// ---------------------------------------------------------------------------
// degree / CSR build
// ---------------------------------------------------------------------------
__global__ void count_deg_kernel(const int* __restrict__ dst, int E) {
    int i = blockIdx.x * blockDim.x + threadIdx.x;
    if (blockIdx.x == 0 && threadIdx.x < 256) g_pub[threadIdx.x] = 0;  // reset lookback
    if (i < E) atomicAdd(&g_deg[dst[i]], 1);
}

// single-kernel exclusive scan of degrees via decoupled lookback;
// also computes dinv and fills row_off/cursor.
__global__ void __launch_bounds__(256)
offsets_lookback_kernel(int n, int E) {
    __shared__ int s[256];
    __shared__ int s_base;
    int t = threadIdx.x;
    int b = blockIdx.x;
    int i = b * 256 + t;
    int d = (i < n) ? g_deg[i] : 0;
    if (i < n) g_dinv[i] = rsqrtf((float)(d + 1));
    s[t] = d;
    __syncthreads();
    for (int o = 1; o < 256; o <<= 1) {
        int v = (t >= o) ? s[t - o] : 0;
        __syncthreads();
        s[t] += v;
        __syncthreads();
    }
    if (t == 0) {
        int total = s[255];
        if (b == 0) {
            atomicExch(&g_pub[0], (total << 2) | 2);
            s_base = 0;
        } else {
            atomicExch(&g_pub[b], (total << 2) | 1);
            int accum = 0;
            int j = b - 1;
            while (true) {
                int p;
                do { p = *(volatile int*)&g_pub[j]; } while ((p & 3) == 0);
                accum += (p >> 2);
                if ((p & 3) == 2) break;
                j--;
            }
            atomicExch(&g_pub[b], ((total + accum) << 2) | 2);
            s_base = accum;
        }
    }
    __syncthreads();
    int excl = s_base + s[t] - d;
    if (i < n) { g_row_off[i] = excl; g_cursor[i] = excl; }
    if (i == n - 1) g_row_off[n] = E;
}

__global__ void fill_csr_kernel(const int* __restrict__ src,
                                const int* __restrict__ dst, int E) {
    int i = blockIdx.x * blockDim.x + threadIdx.x;
    if (i < E) {
        int d = dst[i];
        int pos = atomicAdd(&g_cursor[d], 1);
        g_csr_src[pos] = src[i];
    }
}

// ---------------------------------------------------------------------------
// Single-pass TF32 MMA GEMM; epilogue stores C in fp16 (half2).
// ---------------------------------------------------------------------------
template <int BN>
__global__ void __launch_bounds__(256)
gemm_tf32(const float* __restrict__ A, const float* __restrict__ W,
          __half* __restrict__ C, int M, int NOUT) {
    constexpr int BM = 128, KD = 256;
    constexpr int NTILES = KD / 32;
    constexpr int WARPS_N = BN / 32;
    constexpr int WARPS_M = 8 / WARPS_N;
    constexpr int WM = BM / WARPS_M;
    constexpr int MT = WM / 16;
    constexpr int SA = 36;
    constexpr int ABYTES = BM * SA * 4;
    constexpr int BBYTES = BN * SA * 4;
    constexpr int STAGE = ABYTES + BBYTES;
    constexpr int NBL = BN / 32;

    extern __shared__ char smem_raw[];
    const uint32_t sbase = smem_to_u32(smem_raw);

    const int tid = threadIdx.x;
    const int lane = tid & 31;
    const int wid = tid >> 5;
    const int warp_n = wid % WARPS_N;
    const int warp_m = wid / WARPS_N;
    const int block_m = blockIdx.x * BM;
    const int block_n = blockIdx.y * BN;

    float c[MT][4][4];
#pragma unroll
    for (int i = 0; i < MT; i++)
#pragma unroll
        for (int j = 0; j < 4; j++)
#pragma unroll
            for (int q = 0; q < 4; q++) c[i][j][q] = 0.0f;

    const int a_lrow = lane & 15;
    const int a_lcol = (lane >> 4) * 4;
    const int b_lrow = (lane & 7) + ((lane >> 4) * 8);
    const int b_lcol = ((lane >> 3) & 1) * 4;

    float4 areg[4];
    float4 breg[NBL];
    const int a_r0 = tid >> 3;
    const int a_c4 = tid & 7;

    auto load_global = [&](int t) {
        int k8 = t * 8;
#pragma unroll
        for (int i = 0; i < 4; i++) {
            int gm = block_m + a_r0 + 32 * i;
            int rowc = gm < M ? gm : M - 1;
            areg[i] = __ldg((const float4*)A + (size_t)rowc * 64 + k8 + a_c4);
        }
#pragma unroll
        for (int j = 0; j < NBL; j++) {
            int flat = tid + 256 * j;
            int row = flat >> 3, c4 = flat & 7;
            breg[j] = __ldg((const float4*)W + (size_t)(block_n + row) * 64 + k8 + c4);
        }
    };

    auto store_stage = [&](int st) {
        uint32_t* ab = (uint32_t*)(smem_raw + st * STAGE);
        uint32_t* bb = (uint32_t*)(smem_raw + st * STAGE + ABYTES);
#pragma unroll
        for (int i = 0; i < 4; i++) {
            uint32_t off = (uint32_t)(a_r0 + 32 * i) * SA + a_c4 * 4;
            float4 f = areg[i];
            *(uint4*)(ab + off) = make_uint4(f2tf32(f.x), f2tf32(f.y), f2tf32(f.z), f2tf32(f.w));
        }
#pragma unroll
        for (int j = 0; j < NBL; j++) {
            int flat = tid + 256 * j;
            uint32_t off = (uint32_t)(flat >> 3) * SA + (flat & 7) * 4;
            float4 f = breg[j];
            *(uint4*)(bb + off) = make_uint4(f2tf32(f.x), f2tf32(f.y), f2tf32(f.z), f2tf32(f.w));
        }
    };

    load_global(0);
    store_stage(0);
    __syncthreads();

    for (int t = 0; t < NTILES; t++) {
        int cur = t & 1;
        if (t + 1 < NTILES) load_global(t + 1);

        uint32_t abase = sbase + cur * STAGE;
        uint32_t bbase = abase + ABYTES;

#pragma unroll
        for (int kb = 0; kb < 4; kb++) {
            int koff = kb * 8;
            uint32_t bf[2][4];
#pragma unroll
            for (int ntp = 0; ntp < 2; ntp++) {
                uint32_t addr = bbase + ((uint32_t)(warp_n * 32 + ntp * 16 + b_lrow) * SA +
                                         koff + b_lcol) * 4;
                LDSM_X4(bf[ntp], addr);
            }
#pragma unroll
            for (int mt = 0; mt < MT; mt++) {
                uint32_t af[4];
                uint32_t addr = abase + ((uint32_t)(warp_m * WM + mt * 16 + a_lrow) * SA +
                                         koff + a_lcol) * 4;
                LDSM_X4(af, addr);
#pragma unroll
                for (int ntp = 0; ntp < 2; ntp++) {
                    MMA_TF32(c[mt][ntp * 2 + 0], af, bf[ntp][0], bf[ntp][1]);
                    MMA_TF32(c[mt][ntp * 2 + 1], af, bf[ntp][2], bf[ntp][3]);
                }
            }
        }

        if (t + 1 < NTILES) {
            store_stage((t + 1) & 1);
            __syncthreads();
        }
    }

#pragma unroll
    for (int mt = 0; mt < MT; mt++) {
#pragma unroll
        for (int nt = 0; nt < 4; nt++) {
            int r0 = block_m + warp_m * WM + mt * 16 + (lane >> 2);
            int col = block_n + warp_n * 32 + nt * 8 + (lane & 3) * 2;
            if (r0 < M)
                *(__half2*)&C[(size_t)r0 * NOUT + col] = __floats2half2_rn(c[mt][nt][0], c[mt][nt][1]);
            int r1 = r0 + 8;
            if (r1 < M)
                *(__half2*)&C[(size_t)r1 * NOUT + col] = __floats2half2_rn(c[mt][nt][2], c[mt][nt][3]);
        }
    }
}

// ---------------------------------------------------------------------------
// helpers
// ---------------------------------------------------------------------------
__device__ __forceinline__ void h8_unpack(const uint4& u, float* f) {
    float2 p0 = __half22float2(*(const __half2*)&u.x);
    float2 p1 = __half22float2(*(const __half2*)&u.y);
    float2 p2 = __half22float2(*(const __half2*)&u.z);
    float2 p3 = __half22float2(*(const __half2*)&u.w);
    f[0] = p0.x; f[1] = p0.y; f[2] = p1.x; f[3] = p1.y;
    f[4] = p2.x; f[5] = p2.y; f[6] = p3.x; f[7] = p3.y;
}

// ---------------------------------------------------------------------------
// CSR gather D=256 (fp16 h): one warp per node, 4-edge unroll (MLP 4).
// ---------------------------------------------------------------------------
template <bool ACT>
__global__ void gather_csr_d256(const __half* __restrict__ h,
                                const float* __restrict__ b,
                                float* __restrict__ out, int N) {
    int gw = (blockIdx.x * blockDim.x + threadIdx.x) >> 5;
    int lane = threadIdx.x & 31;
    if (gw >= N) return;

    float dd = g_dinv[gw];
    float w = dd * dd;

    float acc[8], f[8];
    {
        uint4 sv = ((const uint4*)(h + (size_t)gw * DH))[lane];
        h8_unpack(sv, f);
#pragma unroll
        for (int i = 0; i < 8; i++) acc[i] = w * f[i];
    }

    int e0 = g_row_off[gw];
    int e1 = g_row_off[gw + 1];
    int e = e0;
    for (; e + 3 < e1; e += 4) {
        int s0 = __ldg(&g_csr_src[e]);
        int s1 = __ldg(&g_csr_src[e + 1]);
        int s2 = __ldg(&g_csr_src[e + 2]);
        int s3 = __ldg(&g_csr_src[e + 3]);
        float n0 = g_dinv[s0] * dd;
        float n1 = g_dinv[s1] * dd;
        float n2 = g_dinv[s2] * dd;
        float n3 = g_dinv[s3] * dd;
        uint4 u0 = ((const uint4*)(h + (size_t)s0 * DH))[lane];
        uint4 u1 = ((const uint4*)(h + (size_t)s1 * DH))[lane];
        uint4 u2 = ((const uint4*)(h + (size_t)s2 * DH))[lane];
        uint4 u3 = ((const uint4*)(h + (size_t)s3 * DH))[lane];
        h8_unpack(u0, f);
#pragma unroll
        for (int i = 0; i < 8; i++) acc[i] = fmaf(n0, f[i], acc[i]);
        h8_unpack(u1, f);
#pragma unroll
        for (int i = 0; i < 8; i++) acc[i] = fmaf(n1, f[i], acc[i]);
        h8_unpack(u2, f);
#pragma unroll
        for (int i = 0; i < 8; i++) acc[i] = fmaf(n2, f[i], acc[i]);
        h8_unpack(u3, f);
#pragma unroll
        for (int i = 0; i < 8; i++) acc[i] = fmaf(n3, f[i], acc[i]);
    }
    for (; e < e1; e++) {
        int s0 = __ldg(&g_csr_src[e]);
        float n0 = g_dinv[s0] * dd;
        uint4 u0 = ((const uint4*)(h + (size_t)s0 * DH))[lane];
        h8_unpack(u0, f);
#pragma unroll
        for (int i = 0; i < 8; i++) acc[i] = fmaf(n0, f[i], acc[i]);
    }

    const float4* bb = (const float4*)b;
    float4* op = (float4*)(out + (size_t)gw * DH);
    float4 B0 = bb[lane * 2], B1 = bb[lane * 2 + 1];
    float4 o0 = make_float4(acc[0] + B0.x, acc[1] + B0.y, acc[2] + B0.z, acc[3] + B0.w);
    float4 o1 = make_float4(acc[4] + B1.x, acc[5] + B1.y, acc[6] + B1.z, acc[7] + B1.w);
    if (ACT) {
        o0.x = o0.x > 0.f ? o0.x : SLOPE * o0.x;
        o0.y = o0.y > 0.f ? o0.y : SLOPE * o0.y;
        o0.z = o0.z > 0.f ? o0.z : SLOPE * o0.z;
        o0.w = o0.w > 0.f ? o0.w : SLOPE * o0.w;
        o1.x = o1.x > 0.f ? o1.x : SLOPE * o1.x;
        o1.y = o1.y > 0.f ? o1.y : SLOPE * o1.y;
        o1.z = o1.z > 0.f ? o1.z : SLOPE * o1.z;
        o1.w = o1.w > 0.f ? o1.w : SLOPE * o1.w;
    }
    op[lane * 2] = o0;
    op[lane * 2 + 1] = o1;
}

// ---------------------------------------------------------------------------
// CSR gather D=64 (fp16 h): half-warps split even/odd edges, shfl-combine.
// ---------------------------------------------------------------------------
template <bool ACT>
__global__ void gather_csr_d64(const __half* __restrict__ h,
                               const float* __restrict__ b,
                               float* __restrict__ out, int N) {
    int gw = (blockIdx.x * blockDim.x + threadIdx.x) >> 5;
    int lane = threadIdx.x & 31;
    int l16 = lane & 15;
    int half = lane >> 4;
    if (gw >= N) return;

    float dd = g_dinv[gw];
    int e0 = g_row_off[gw];
    int e1 = g_row_off[gw + 1];

    float acc[4] = {0.f, 0.f, 0.f, 0.f};
    int e = e0 + half;
    for (; e + 2 < e1; e += 4) {
        int s0 = __ldg(&g_csr_src[e]);
        int s1 = __ldg(&g_csr_src[e + 2]);
        float n0 = g_dinv[s0] * dd;
        float n1 = g_dinv[s1] * dd;
        uint2 u0 = ((const uint2*)(h + (size_t)s0 * DOUT))[l16];
        uint2 u1 = ((const uint2*)(h + (size_t)s1 * DOUT))[l16];
        float2 a0 = __half22float2(*(const __half2*)&u0.x);
        float2 a1 = __half22float2(*(const __half2*)&u0.y);
        float2 c0 = __half22float2(*(const __half2*)&u1.x);
        float2 c1 = __half22float2(*(const __half2*)&u1.y);
        acc[0] = fmaf(n0, a0.x, acc[0]); acc[1] = fmaf(n0, a0.y, acc[1]);
        acc[2] = fmaf(n0, a1.x, acc[2]); acc[3] = fmaf(n0, a1.y, acc[3]);
        acc[0] = fmaf(n1, c0.x, acc[0]); acc[1] = fmaf(n1, c0.y, acc[1]);
        acc[2] = fmaf(n1, c1.x, acc[2]); acc[3] = fmaf(n1, c1.y, acc[3]);
    }
    for (; e < e1; e += 2) {
        int s = __ldg(&g_csr_src[e]);
        float norm = g_dinv[s] * dd;
        uint2 u = ((const uint2*)(h + (size_t)s * DOUT))[l16];
        float2 p0 = __half22float2(*(const __half2*)&u.x);
        float2 p1 = __half22float2(*(const __half2*)&u.y);
        acc[0] = fmaf(norm, p0.x, acc[0]);
        acc[1] = fmaf(norm, p0.y, acc[1]);
        acc[2] = fmaf(norm, p1.x, acc[2]);
        acc[3] = fmaf(norm, p1.y, acc[3]);
    }
#pragma unroll
    for (int i = 0; i < 4; i++)
        acc[i] += __shfl_xor_sync(0xffffffffu, acc[i], 16);

    if (half == 0) {
        float w = dd * dd;
        uint2 u = ((const uint2*)(h + (size_t)gw * DOUT))[l16];
        float2 p0 = __half22float2(*(const __half2*)&u.x);
        float2 p1 = __half22float2(*(const __half2*)&u.y);
        float4 B = ((const float4*)b)[l16];
        float4 o;
        o.x = fmaf(w, p0.x, acc[0]) + B.x;
        o.y = fmaf(w, p0.y, acc[1]) + B.y;
        o.z = fmaf(w, p1.x, acc[2]) + B.z;
        o.w = fmaf(w, p1.y, acc[3]) + B.w;
        if (ACT) {
            o.x = o.x > 0.f ? o.x : SLOPE * o.x;
            o.y = o.y > 0.f ? o.y : SLOPE * o.y;
            o.z = o.z > 0.f ? o.z : SLOPE * o.z;
            o.w = o.w > 0.f ? o.w : SLOPE * o.w;
        }
        ((float4*)(out + (size_t)gw * DOUT))[l16] = o;
    }
}

// ---------------------------------------------------------------------------
// launch
// ---------------------------------------------------------------------------
extern "C" void kernel_launch(void* const* d_in, const int* in_sizes, int n_in,
                              void* d_out, int out_size) {
    const float* x  = (const float*)d_in[0];
    const int*   ei = (const int*)d_in[1];
    const float* W1 = (const float*)d_in[2];
    const float* b1 = (const float*)d_in[3];
    const float* W2 = (const float*)d_in[4];
    const float* b2 = (const float*)d_in[5];
    const float* W3 = (const float*)d_in[6];
    const float* b3 = (const float*)d_in[7];
    float* out = (float*)d_out;

    const int N = in_sizes[0] / DH;
    const int E = in_sizes[1] / 2;
    const int* src = ei;
    const int* dstp = ei + E;

    float* h1 = out;
    float* h2 = out + (size_t)N * DH;
    float* lg = out + 2 * (size_t)N * DH;

    __half* hbuf = nullptr;
    cudaGetSymbolAddress((void**)&hbuf, g_h);
    int* degp = nullptr;
    cudaGetSymbolAddress((void**)&degp, g_deg);

    const int SMEM128 = 2 * (128 * 36 * 4 + 128 * 36 * 4);  // 73728
    const int SMEM64  = 2 * (128 * 36 * 4 + 64 * 36 * 4);   // 55296
    cudaFuncSetAttribute(gemm_tf32<128>, cudaFuncAttributeMaxDynamicSharedMemorySize, SMEM128);
    cudaFuncSetAttribute(gemm_tf32<64>,  cudaFuncAttributeMaxDynamicSharedMemorySize, SMEM64);

    // --- degree / dinv / CSR (single-pass lookback scan) ---
    const int NB = (N + 255) / 256;
    cudaMemsetAsync(degp, 0, N * sizeof(int));
    count_deg_kernel<<<(E + 255) / 256, 256>>>(dstp, E);
    offsets_lookback_kernel<<<NB, 256>>>(N, E);
    fill_csr_kernel<<<(E + 255) / 256, 256>>>(src, dstp, E);

    const int gather_blocks = (N + 7) / 8;
    const int tiles_m = (N + 127) / 128;

    // --- layer 1 ---
    gemm_tf32<128><<<dim3(tiles_m, DH / 128), 256, SMEM128>>>(x, W1, hbuf, N, DH);
    gather_csr_d256<true><<<gather_blocks, 256>>>(hbuf, b1, h1, N);

    // --- layer 2 ---
    gemm_tf32<128><<<dim3(tiles_m, DH / 128), 256, SMEM128>>>(h1, W2, hbuf, N, DH);
    gather_csr_d256<true><<<gather_blocks, 256>>>(hbuf, b2, h2, N);

    // --- layer 3 ---
    gemm_tf32<64><<<dim3(tiles_m, DOUT / 64), 256, SMEM64>>>(h2, W3, hbuf, N, DOUT);
    gather_csr_d64<false><<<gather_blocks, 256>>>(hbuf, b3, lg, N);
}

// round 15
// speedup vs baseline: 1.1274x; 1.1274x over previous
#include <cuda_runtime.h>
#include <cuda_fp16.h>
#include <cstdint>

#define N_NODES 50000
#define E_MAX   800000
#define DH 256
#define DOUT 64
#define SLOPE 0.01f

// ---------------------------------------------------------------------------
// Scratch (allocation-free rule: __device__ globals)
// ---------------------------------------------------------------------------
__device__ __half g_h[(size_t)N_NODES * DH];    // GEMM output per layer (fp16)
__device__ __half g_a16[(size_t)N_NODES * DH];  // fp16 GEMM input (x, then h1, h2)
__device__ __half g_w1[DH * DH], g_w2[DH * DH], g_w3[DOUT * DH];
__device__ int    g_deg[N_NODES];
__device__ float  g_dinv[N_NODES];
__device__ int    g_row_off[N_NODES + 1];
__device__ int    g_cursor[N_NODES];
__device__ int    g_csr_src[E_MAX];
__device__ int    g_pub[256];                   // lookback scan: (sum<<2)|flag

__device__ __forceinline__ uint32_t smem_to_u32(const void* p) {
    uint32_t a;
    asm("{ .reg .u64 t; cvta.to.shared.u64 t, %1; cvt.u32.u64 %0, t; }" : "=r"(a) : "l"(p));
    return a;
}

#define LDSM_X4(R, ADDR) \
    asm volatile("ldmatrix.sync.aligned.m8n8.x4.shared.b16 {%0,%1,%2,%3}, [%4];" \
                 : "=r"((R)[0]), "=r"((R)[1]), "=r"((R)[2]), "=r"((R)[3]) : "r"(ADDR))

#define MMA_F16(C, A, B0, B1) \
    asm volatile("mma.sync.aligned.m16n8k16.row.col.f32.f16.f16.f32 " \
                 "{%0,%1,%2,%3}, {%4,%5,%6,%7}, {%8,%9}, {%0,%1,%2,%3};" \
                 : "+f"((C)[0]), "+f"((C)[1]), "+f"((C)[2]), "+f"((C)[3]) \
                 : "r"((A)[0]), "r"((A)[1]), "r"((A)[2]), "r"((A)[3]), "r"(B0), "r"(B1))

// ---------------------------------------------------------------------------
// fp32 -> fp16 convert (float4 -> uint2 of half2)
// ---------------------------------------------------------------------------
__global__ void f2h_kernel(const float* __restrict__ in, __half* __restrict__ out, int total4) {
    int i = blockIdx.x * blockDim.x + threadIdx.x;
    if (i >= total4) return;
    float4 v = ((const float4*)in)[i];
    __half2 a = __floats2half2_rn(v.x, v.y);
    __half2 b = __floats2half2_rn(v.z, v.w);
    uint2 o = make_uint2(*(uint32_t*)&a, *(uint32_t*)&b);
    ((uint2*)out)[i] = o;
}

// ---------------------------------------------------------------------------
// degree / CSR build
// ---------------------------------------------------------------------------
__global__ void count_deg_kernel(const int* __restrict__ dst, int E) {
    int i = blockIdx.x * blockDim.x + threadIdx.x;
    if (blockIdx.x == 0 && threadIdx.x < 256) g_pub[threadIdx.x] = 0;  // reset lookback
    if (i < E) atomicAdd(&g_deg[dst[i]], 1);
}

__global__ void __launch_bounds__(256)
offsets_lookback_kernel(int n, int E) {
    __shared__ int s[256];
    __shared__ int s_base;
    int t = threadIdx.x;
    int b = blockIdx.x;
    int i = b * 256 + t;
    int d = (i < n) ? g_deg[i] : 0;
    if (i < n) g_dinv[i] = rsqrtf((float)(d + 1));
    s[t] = d;
    __syncthreads();
    for (int o = 1; o < 256; o <<= 1) {
        int v = (t >= o) ? s[t - o] : 0;
        __syncthreads();
        s[t] += v;
        __syncthreads();
    }
    if (t == 0) {
        int total = s[255];
        if (b == 0) {
            atomicExch(&g_pub[0], (total << 2) | 2);
            s_base = 0;
        } else {
            atomicExch(&g_pub[b], (total << 2) | 1);
            int accum = 0;
            int j = b - 1;
            while (true) {
                int p;
                do { p = *(volatile int*)&g_pub[j]; } while ((p & 3) == 0);
                accum += (p >> 2);
                if ((p & 3) == 2) break;
                j--;
            }
            atomicExch(&g_pub[b], ((total + accum) << 2) | 2);
            s_base = accum;
        }
    }
    __syncthreads();
    int excl = s_base + s[t] - d;
    if (i < n) { g_row_off[i] = excl; g_cursor[i] = excl; }
    if (i == n - 1) g_row_off[n] = E;
}

__global__ void fill_csr_kernel(const int* __restrict__ src,
                                const int* __restrict__ dst, int E) {
    int i = blockIdx.x * blockDim.x + threadIdx.x;
    if (i < E) {
        int d = dst[i];
        int pos = atomicAdd(&g_cursor[d], 1);
        g_csr_src[pos] = src[i];
    }
}

// ---------------------------------------------------------------------------
// fp16 MMA GEMM: C[M,NOUT] = A[M,256] @ W[NOUT,256]^T, fp32 accum, fp16 out.
// mma.sync.m16n8k16.f16, single pass. BM=128, BK=32, 256 threads (8 warps).
// Fragment/SMEM layout identical to the validated R10 bf16 kernel (SA=40).
// ---------------------------------------------------------------------------
template <int BN>
__global__ void __launch_bounds__(256)
gemm_f16(const __half* __restrict__ A, const __half* __restrict__ W,
         __half* __restrict__ C, int M, int NOUT) {
    constexpr int BM = 128, BK = 32, KD = 256;
    constexpr int NTILES = KD / BK;                  // 8
    constexpr int WARPS_N = BN / 32;
    constexpr int WARPS_M = 8 / WARPS_N;
    constexpr int WM = BM / WARPS_M;
    constexpr int MT = WM / 16;
    constexpr int SA = 40;                           // padded stride (halves)
    constexpr int ABYTES = BM * SA * 2;              // 10240
    constexpr int BBYTES = BN * SA * 2;
    constexpr int STAGE = ABYTES + BBYTES;
    constexpr int NAL = (BM * BK) / (4 * 256);       // uint2 A-loads per thread (4)
    constexpr int NBL = (BN * BK) / (4 * 256);       // uint2 B-loads per thread

    extern __shared__ char smem_raw[];
    const uint32_t sbase = smem_to_u32(smem_raw);

    const int tid = threadIdx.x;
    const int lane = tid & 31;
    const int wid = tid >> 5;
    const int warp_n = wid % WARPS_N;
    const int warp_m = wid / WARPS_N;
    const int l16 = lane & 15;
    const int lg = lane >> 4;
    const int block_m = blockIdx.x * BM;
    const int block_n = blockIdx.y * BN;

    float c[MT][4][4];
#pragma unroll
    for (int i = 0; i < MT; i++)
#pragma unroll
        for (int j = 0; j < 4; j++)
#pragma unroll
            for (int q = 0; q < 4; q++) c[i][j][q] = 0.0f;

    // staging registers (raw fp16 — no conversion)
    uint2 areg[NAL], breg[NBL];

    auto load_global = [&](int t) {
        int k2 = t * 8;  // uint2 (4 halves) offset along K (32 halves = 8 uint2)
#pragma unroll
        for (int j = 0; j < NAL; j++) {
            int flat = tid + 256 * j;
            int row = flat >> 3, c2 = flat & 7;
            int gm = block_m + row;
            int rowc = gm < M ? gm : M - 1;
            areg[j] = __ldg((const uint2*)A + (size_t)rowc * 64 + k2 + c2);
        }
#pragma unroll
        for (int j = 0; j < NBL; j++) {
            int flat = tid + 256 * j;
            int row = flat >> 3, c2 = flat & 7;
            breg[j] = __ldg((const uint2*)W + (size_t)(block_n + row) * 64 + k2 + c2);
        }
    };

    auto store_stage = [&](int st) {
        char* ab = smem_raw + st * STAGE;
        char* bb = ab + ABYTES;
#pragma unroll
        for (int j = 0; j < NAL; j++) {
            int flat = tid + 256 * j;
            uint32_t off = (uint32_t)(flat >> 3) * (SA * 2) + (flat & 7) * 8;
            *(uint2*)(ab + off) = areg[j];
        }
#pragma unroll
        for (int j = 0; j < NBL; j++) {
            int flat = tid + 256 * j;
            uint32_t off = (uint32_t)(flat >> 3) * (SA * 2) + (flat & 7) * 8;
            *(uint2*)(bb + off) = breg[j];
        }
    };

    load_global(0);
    store_stage(0);
    __syncthreads();

    for (int t = 0; t < NTILES; t++) {
        int cur = t & 1;
        if (t + 1 < NTILES) load_global(t + 1);

        uint32_t abase = sbase + cur * STAGE;
        uint32_t bbase = abase + ABYTES;

#pragma unroll
        for (int kb = 0; kb < 2; kb++) {
            uint32_t koff = (uint32_t)(kb * 16 + lg * 8) * 2;
            uint32_t bf[2][4];
#pragma unroll
            for (int ntp = 0; ntp < 2; ntp++) {
                uint32_t roff = (uint32_t)(warp_n * 32 + ntp * 16 + l16) * (SA * 2) + koff;
                LDSM_X4(bf[ntp], bbase + roff);
            }
#pragma unroll
            for (int mt = 0; mt < MT; mt++) {
                uint32_t af[4];
                uint32_t roff = (uint32_t)(warp_m * WM + mt * 16 + l16) * (SA * 2) + koff;
                LDSM_X4(af, abase + roff);
#pragma unroll
                for (int ntp = 0; ntp < 2; ntp++) {
#pragma unroll
                    for (int sub = 0; sub < 2; sub++) {
                        int nt = ntp * 2 + sub;
                        MMA_F16(c[mt][nt], af, bf[ntp][sub], bf[ntp][sub + 2]);
                    }
                }
            }
        }

        if (t + 1 < NTILES) {
            store_stage((t + 1) & 1);
            __syncthreads();
        }
    }

    // epilogue: half2 per quad -> fp16 C
#pragma unroll
    for (int mt = 0; mt < MT; mt++) {
#pragma unroll
        for (int nt = 0; nt < 4; nt++) {
            int r0 = block_m + warp_m * WM + mt * 16 + (lane >> 2);
            int col = block_n + warp_n * 32 + nt * 8 + (lane & 3) * 2;
            if (r0 < M)
                *(__half2*)&C[(size_t)r0 * NOUT + col] = __floats2half2_rn(c[mt][nt][0], c[mt][nt][1]);
            int r1 = r0 + 8;
            if (r1 < M)
                *(__half2*)&C[(size_t)r1 * NOUT + col] = __floats2half2_rn(c[mt][nt][2], c[mt][nt][3]);
        }
    }
}

// ---------------------------------------------------------------------------
// helpers
// ---------------------------------------------------------------------------
__device__ __forceinline__ void h8_unpack(const uint4& u, float* f) {
    float2 p0 = __half22float2(*(const __half2*)&u.x);
    float2 p1 = __half22float2(*(const __half2*)&u.y);
    float2 p2 = __half22float2(*(const __half2*)&u.z);
    float2 p3 = __half22float2(*(const __half2*)&u.w);
    f[0] = p0.x; f[1] = p0.y; f[2] = p1.x; f[3] = p1.y;
    f[4] = p2.x; f[5] = p2.y; f[6] = p3.x; f[7] = p3.y;
}

// ---------------------------------------------------------------------------
// CSR gather D=256 (fp16 h): writes fp32 out AND fp16 copy (next GEMM input).
// ---------------------------------------------------------------------------
template <bool ACT>
__global__ void gather_csr_d256(const __half* __restrict__ h,
                                const float* __restrict__ b,
                                float* __restrict__ out,
                                __half* __restrict__ hcopy, int N) {
    int gw = (blockIdx.x * blockDim.x + threadIdx.x) >> 5;
    int lane = threadIdx.x & 31;
    if (gw >= N) return;

    float dd = g_dinv[gw];
    float w = dd * dd;

    float acc[8], f[8];
    {
        uint4 sv = ((const uint4*)(h + (size_t)gw * DH))[lane];
        h8_unpack(sv, f);
#pragma unroll
        for (int i = 0; i < 8; i++) acc[i] = w * f[i];
    }

    int e0 = g_row_off[gw];
    int e1 = g_row_off[gw + 1];
    int e = e0;
    for (; e + 1 < e1; e += 2) {
        int s0 = __ldg(&g_csr_src[e]);
        int s1 = __ldg(&g_csr_src[e + 1]);
        float n0 = g_dinv[s0] * dd;
        float n1 = g_dinv[s1] * dd;
        uint4 u0 = ((const uint4*)(h + (size_t)s0 * DH))[lane];
        uint4 u1 = ((const uint4*)(h + (size_t)s1 * DH))[lane];
        h8_unpack(u0, f);
#pragma unroll
        for (int i = 0; i < 8; i++) acc[i] = fmaf(n0, f[i], acc[i]);
        h8_unpack(u1, f);
#pragma unroll
        for (int i = 0; i < 8; i++) acc[i] = fmaf(n1, f[i], acc[i]);
    }
    if (e < e1) {
        int s0 = __ldg(&g_csr_src[e]);
        float n0 = g_dinv[s0] * dd;
        uint4 u0 = ((const uint4*)(h + (size_t)s0 * DH))[lane];
        h8_unpack(u0, f);
#pragma unroll
        for (int i = 0; i < 8; i++) acc[i] = fmaf(n0, f[i], acc[i]);
    }

    const float4* bb = (const float4*)b;
    float4 B0 = bb[lane * 2], B1 = bb[lane * 2 + 1];
    float o[8];
    o[0] = acc[0] + B0.x; o[1] = acc[1] + B0.y; o[2] = acc[2] + B0.z; o[3] = acc[3] + B0.w;
    o[4] = acc[4] + B1.x; o[5] = acc[5] + B1.y; o[6] = acc[6] + B1.z; o[7] = acc[7] + B1.w;
    if (ACT) {
#pragma unroll
        for (int i = 0; i < 8; i++) o[i] = o[i] > 0.f ? o[i] : SLOPE * o[i];
    }
    float4* op = (float4*)(out + (size_t)gw * DH);
    op[lane * 2]     = make_float4(o[0], o[1], o[2], o[3]);
    op[lane * 2 + 1] = make_float4(o[4], o[5], o[6], o[7]);
    // fp16 copy for the next layer's GEMM
    __half2 h0 = __floats2half2_rn(o[0], o[1]);
    __half2 h1 = __floats2half2_rn(o[2], o[3]);
    __half2 h2 = __floats2half2_rn(o[4], o[5]);
    __half2 h3 = __floats2half2_rn(o[6], o[7]);
    uint4 pack = make_uint4(*(uint32_t*)&h0, *(uint32_t*)&h1, *(uint32_t*)&h2, *(uint32_t*)&h3);
    ((uint4*)(hcopy + (size_t)gw * DH))[lane] = pack;
}

// ---------------------------------------------------------------------------
// CSR gather D=64 (fp16 h): half-warps split even/odd edges, shfl-combine.
// ---------------------------------------------------------------------------
template <bool ACT>
__global__ void gather_csr_d64(const __half* __restrict__ h,
                               const float* __restrict__ b,
                               float* __restrict__ out, int N) {
    int gw = (blockIdx.x * blockDim.x + threadIdx.x) >> 5;
    int lane = threadIdx.x & 31;
    int l16 = lane & 15;
    int half = lane >> 4;
    if (gw >= N) return;

    float dd = g_dinv[gw];
    int e0 = g_row_off[gw];
    int e1 = g_row_off[gw + 1];

    float acc[4] = {0.f, 0.f, 0.f, 0.f};
    for (int e = e0 + half; e < e1; e += 2) {
        int s = __ldg(&g_csr_src[e]);
        float norm = g_dinv[s] * dd;
        uint2 u = ((const uint2*)(h + (size_t)s * DOUT))[l16];
        float2 p0 = __half22float2(*(const __half2*)&u.x);
        float2 p1 = __half22float2(*(const __half2*)&u.y);
        acc[0] = fmaf(norm, p0.x, acc[0]);
        acc[1] = fmaf(norm, p0.y, acc[1]);
        acc[2] = fmaf(norm, p1.x, acc[2]);
        acc[3] = fmaf(norm, p1.y, acc[3]);
    }
#pragma unroll
    for (int i = 0; i < 4; i++)
        acc[i] += __shfl_xor_sync(0xffffffffu, acc[i], 16);

    if (half == 0) {
        float w = dd * dd;
        uint2 u = ((const uint2*)(h + (size_t)gw * DOUT))[l16];
        float2 p0 = __half22float2(*(const __half2*)&u.x);
        float2 p1 = __half22float2(*(const __half2*)&u.y);
        float4 B = ((const float4*)b)[l16];
        float4 o;
        o.x = fmaf(w, p0.x, acc[0]) + B.x;
        o.y = fmaf(w, p0.y, acc[1]) + B.y;
        o.z = fmaf(w, p1.x, acc[2]) + B.z;
        o.w = fmaf(w, p1.y, acc[3]) + B.w;
        if (ACT) {
            o.x = o.x > 0.f ? o.x : SLOPE * o.x;
            o.y = o.y > 0.f ? o.y : SLOPE * o.y;
            o.z = o.z > 0.f ? o.z : SLOPE * o.z;
            o.w = o.w > 0.f ? o.w : SLOPE * o.w;
        }
        ((float4*)(out + (size_t)gw * DOUT))[l16] = o;
    }
}

// ---------------------------------------------------------------------------
// launch
// ---------------------------------------------------------------------------
extern "C" void kernel_launch(void* const* d_in, const int* in_sizes, int n_in,
                              void* d_out, int out_size) {
    const float* x  = (const float*)d_in[0];
    const int*   ei = (const int*)d_in[1];
    const float* W1 = (const float*)d_in[2];
    const float* b1 = (const float*)d_in[3];
    const float* W2 = (const float*)d_in[4];
    const float* b2 = (const float*)d_in[5];
    const float* W3 = (const float*)d_in[6];
    const float* b3 = (const float*)d_in[7];
    float* out = (float*)d_out;

    const int N = in_sizes[0] / DH;
    const int E = in_sizes[1] / 2;
    const int* src = ei;
    const int* dstp = ei + E;

    float* h1 = out;
    float* h2 = out + (size_t)N * DH;
    float* lg = out + 2 * (size_t)N * DH;

    __half *hbuf, *a16, *w1h, *w2h, *w3h;
    cudaGetSymbolAddress((void**)&hbuf, g_h);
    cudaGetSymbolAddress((void**)&a16, g_a16);
    cudaGetSymbolAddress((void**)&w1h, g_w1);
    cudaGetSymbolAddress((void**)&w2h, g_w2);
    cudaGetSymbolAddress((void**)&w3h, g_w3);
    int* degp = nullptr;
    cudaGetSymbolAddress((void**)&degp, g_deg);

    const int SMEM128 = 2 * (128 * 40 * 2 + 128 * 40 * 2);  // 40960
    const int SMEM64  = 2 * (128 * 40 * 2 + 64 * 40 * 2);   // 30720
    cudaFuncSetAttribute(gemm_f16<128>, cudaFuncAttributeMaxDynamicSharedMemorySize, SMEM128);
    cudaFuncSetAttribute(gemm_f16<64>,  cudaFuncAttributeMaxDynamicSharedMemorySize, SMEM64);

    // --- fp16 operand prep ---
    f2h_kernel<<<(N * (DH / 4) + 255) / 256, 256>>>(x, a16, N * (DH / 4));
    f2h_kernel<<<(DH * DH / 4 + 255) / 256, 256>>>(W1, w1h, DH * DH / 4);
    f2h_kernel<<<(DH * DH / 4 + 255) / 256, 256>>>(W2, w2h, DH * DH / 4);
    f2h_kernel<<<(DOUT * DH / 4 + 255) / 256, 256>>>(W3, w3h, DOUT * DH / 4);

    // --- degree / dinv / CSR ---
    const int NB = (N + 255) / 256;
    cudaMemsetAsync(degp, 0, N * sizeof(int));
    count_deg_kernel<<<(E + 255) / 256, 256>>>(dstp, E);
    offsets_lookback_kernel<<<NB, 256>>>(N, E);
    fill_csr_kernel<<<(E + 255) / 256, 256>>>(src, dstp, E);

    const int gather_blocks = (N + 7) / 8;
    const int tiles_m = (N + 127) / 128;

    // --- layer 1 ---
    gemm_f16<128><<<dim3(tiles_m, DH / 128), 256, SMEM128>>>(a16, w1h, hbuf, N, DH);
    gather_csr_d256<true><<<gather_blocks, 256>>>(hbuf, b1, h1, a16, N);

    // --- layer 2 ---
    gemm_f16<128><<<dim3(tiles_m, DH / 128), 256, SMEM128>>>(a16, w2h, hbuf, N, DH);
    gather_csr_d256<true><<<gather_blocks, 256>>>(hbuf, b2, h2, a16, N);

    // --- layer 3 ---
    gemm_f16<64><<<dim3(tiles_m, DOUT / 64), 256, SMEM64>>>(a16, w3h, hbuf, N, DOUT);
    gather_csr_d64<false><<<gather_blocks, 256>>>(hbuf, b3, lg, N);
}

// round 16
// speedup vs baseline: 1.1981x; 1.0627x over previous
#include <cuda_runtime.h>
#include <cuda_fp16.h>
#include <cstdint>

#define N_NODES 50000
#define E_MAX   800000
#define DH 256
#define DOUT 64
#define SLOPE 0.01f

// ---------------------------------------------------------------------------
// Scratch (allocation-free rule: __device__ globals)
// ---------------------------------------------------------------------------
__device__ __half g_h[(size_t)N_NODES * DH];    // GEMM output per layer (fp16)
__device__ __half g_a16[(size_t)N_NODES * DH];  // fp16 GEMM input (x, then h1, h2)
__device__ __half g_w1[DH * DH], g_w2[DH * DH], g_w3[DOUT * DH];
__device__ int    g_deg[N_NODES];
__device__ float  g_dinv[N_NODES];
__device__ int    g_row_off[N_NODES + 1];
__device__ int    g_cursor[N_NODES];
__device__ int    g_csr_src[E_MAX];
__device__ int    g_pub[256];                   // lookback scan: (sum<<2)|flag

__device__ __forceinline__ uint32_t smem_to_u32(const void* p) {
    uint32_t a;
    asm("{ .reg .u64 t; cvta.to.shared.u64 t, %1; cvt.u32.u64 %0, t; }" : "=r"(a) : "l"(p));
    return a;
}

#define LDSM_X4(R, ADDR) \
    asm volatile("ldmatrix.sync.aligned.m8n8.x4.shared.b16 {%0,%1,%2,%3}, [%4];" \
                 : "=r"((R)[0]), "=r"((R)[1]), "=r"((R)[2]), "=r"((R)[3]) : "r"(ADDR))

#define MMA_F16(C, A, B0, B1) \
    asm volatile("mma.sync.aligned.m16n8k16.row.col.f32.f16.f16.f32 " \
                 "{%0,%1,%2,%3}, {%4,%5,%6,%7}, {%8,%9}, {%0,%1,%2,%3};" \
                 : "+f"((C)[0]), "+f"((C)[1]), "+f"((C)[2]), "+f"((C)[3]) \
                 : "r"((A)[0]), "r"((A)[1]), "r"((A)[2]), "r"((A)[3]), "r"(B0), "r"(B1))

// ---------------------------------------------------------------------------
// fp32 -> fp16 convert (float4 -> uint2 of half2)
// ---------------------------------------------------------------------------
__global__ void f2h_kernel(const float* __restrict__ in, __half* __restrict__ out, int total4) {
    int i = blockIdx.x * blockDim.x + threadIdx.x;
    if (i >= total4) return;
    float4 v = ((const float4*)in)[i];
    __half2 a = __floats2half2_rn(v.x, v.y);
    __half2 b = __floats2half2_rn(v.z, v.w);
    uint2 o = make_uint2(*(uint32_t*)&a, *(uint32_t*)&b);
    ((uint2*)out)[i] = o;
}

// ---------------------------------------------------------------------------
// degree / CSR build
// ---------------------------------------------------------------------------
__global__ void count_deg_kernel(const int* __restrict__ dst, int E) {
    int i = blockIdx.x * blockDim.x + threadIdx.x;
    if (blockIdx.x == 0 && threadIdx.x < 256) g_pub[threadIdx.x] = 0;  // reset lookback
    if (i < E) atomicAdd(&g_deg[dst[i]], 1);
}

__global__ void __launch_bounds__(256)
offsets_lookback_kernel(int n, int E) {
    __shared__ int s[256];
    __shared__ int s_base;
    int t = threadIdx.x;
    int b = blockIdx.x;
    int i = b * 256 + t;
    int d = (i < n) ? g_deg[i] : 0;
    if (i < n) g_dinv[i] = rsqrtf((float)(d + 1));
    s[t] = d;
    __syncthreads();
    for (int o = 1; o < 256; o <<= 1) {
        int v = (t >= o) ? s[t - o] : 0;
        __syncthreads();
        s[t] += v;
        __syncthreads();
    }
    if (t == 0) {
        int total = s[255];
        if (b == 0) {
            atomicExch(&g_pub[0], (total << 2) | 2);
            s_base = 0;
        } else {
            atomicExch(&g_pub[b], (total << 2) | 1);
            int accum = 0;
            int j = b - 1;
            while (true) {
                int p;
                do { p = *(volatile int*)&g_pub[j]; } while ((p & 3) == 0);
                accum += (p >> 2);
                if ((p & 3) == 2) break;
                j--;
            }
            atomicExch(&g_pub[b], ((total + accum) << 2) | 2);
            s_base = accum;
        }
    }
    __syncthreads();
    int excl = s_base + s[t] - d;
    if (i < n) { g_row_off[i] = excl; g_cursor[i] = excl; }
    if (i == n - 1) g_row_off[n] = E;
}

__global__ void fill_csr_kernel(const int* __restrict__ src,
                                const int* __restrict__ dst, int E) {
    int i = blockIdx.x * blockDim.x + threadIdx.x;
    if (i < E) {
        int d = dst[i];
        int pos = atomicAdd(&g_cursor[d], 1);
        g_csr_src[pos] = src[i];
    }
}

// ---------------------------------------------------------------------------
// fp16 MMA GEMM: C[M,NOUT] = A[M,256] @ W[NOUT,256]^T, fp32 accum, fp16 out.
// ---------------------------------------------------------------------------
template <int BN>
__global__ void __launch_bounds__(256)
gemm_f16(const __half* __restrict__ A, const __half* __restrict__ W,
         __half* __restrict__ C, int M, int NOUT) {
    constexpr int BM = 128, BK = 32, KD = 256;
    constexpr int NTILES = KD / BK;                  // 8
    constexpr int WARPS_N = BN / 32;
    constexpr int WARPS_M = 8 / WARPS_N;
    constexpr int WM = BM / WARPS_M;
    constexpr int MT = WM / 16;
    constexpr int SA = 40;                           // padded stride (halves)
    constexpr int ABYTES = BM * SA * 2;              // 10240
    constexpr int BBYTES = BN * SA * 2;
    constexpr int STAGE = ABYTES + BBYTES;
    constexpr int NAL = (BM * BK) / (4 * 256);       // uint2 A-loads per thread (4)
    constexpr int NBL = (BN * BK) / (4 * 256);       // uint2 B-loads per thread

    extern __shared__ char smem_raw[];
    const uint32_t sbase = smem_to_u32(smem_raw);

    const int tid = threadIdx.x;
    const int lane = tid & 31;
    const int wid = tid >> 5;
    const int warp_n = wid % WARPS_N;
    const int warp_m = wid / WARPS_N;
    const int l16 = lane & 15;
    const int lg = lane >> 4;
    const int block_m = blockIdx.x * BM;
    const int block_n = blockIdx.y * BN;

    float c[MT][4][4];
#pragma unroll
    for (int i = 0; i < MT; i++)
#pragma unroll
        for (int j = 0; j < 4; j++)
#pragma unroll
            for (int q = 0; q < 4; q++) c[i][j][q] = 0.0f;

    uint2 areg[NAL], breg[NBL];

    auto load_global = [&](int t) {
        int k2 = t * 8;
#pragma unroll
        for (int j = 0; j < NAL; j++) {
            int flat = tid + 256 * j;
            int row = flat >> 3, c2 = flat & 7;
            int gm = block_m + row;
            int rowc = gm < M ? gm : M - 1;
            areg[j] = __ldg((const uint2*)A + (size_t)rowc * 64 + k2 + c2);
        }
#pragma unroll
        for (int j = 0; j < NBL; j++) {
            int flat = tid + 256 * j;
            int row = flat >> 3, c2 = flat & 7;
            breg[j] = __ldg((const uint2*)W + (size_t)(block_n + row) * 64 + k2 + c2);
        }
    };

    auto store_stage = [&](int st) {
        char* ab = smem_raw + st * STAGE;
        char* bb = ab + ABYTES;
#pragma unroll
        for (int j = 0; j < NAL; j++) {
            int flat = tid + 256 * j;
            uint32_t off = (uint32_t)(flat >> 3) * (SA * 2) + (flat & 7) * 8;
            *(uint2*)(ab + off) = areg[j];
        }
#pragma unroll
        for (int j = 0; j < NBL; j++) {
            int flat = tid + 256 * j;
            uint32_t off = (uint32_t)(flat >> 3) * (SA * 2) + (flat & 7) * 8;
            *(uint2*)(bb + off) = breg[j];
        }
    };

    load_global(0);
    store_stage(0);
    __syncthreads();

    for (int t = 0; t < NTILES; t++) {
        int cur = t & 1;
        if (t + 1 < NTILES) load_global(t + 1);

        uint32_t abase = sbase + cur * STAGE;
        uint32_t bbase = abase + ABYTES;

#pragma unroll
        for (int kb = 0; kb < 2; kb++) {
            uint32_t koff = (uint32_t)(kb * 16 + lg * 8) * 2;
            uint32_t bf[2][4];
#pragma unroll
            for (int ntp = 0; ntp < 2; ntp++) {
                uint32_t roff = (uint32_t)(warp_n * 32 + ntp * 16 + l16) * (SA * 2) + koff;
                LDSM_X4(bf[ntp], bbase + roff);
            }
#pragma unroll
            for (int mt = 0; mt < MT; mt++) {
                uint32_t af[4];
                uint32_t roff = (uint32_t)(warp_m * WM + mt * 16 + l16) * (SA * 2) + koff;
                LDSM_X4(af, abase + roff);
#pragma unroll
                for (int ntp = 0; ntp < 2; ntp++) {
#pragma unroll
                    for (int sub = 0; sub < 2; sub++) {
                        int nt = ntp * 2 + sub;
                        MMA_F16(c[mt][nt], af, bf[ntp][sub], bf[ntp][sub + 2]);
                    }
                }
            }
        }

        if (t + 1 < NTILES) {
            store_stage((t + 1) & 1);
            __syncthreads();
        }
    }

#pragma unroll
    for (int mt = 0; mt < MT; mt++) {
#pragma unroll
        for (int nt = 0; nt < 4; nt++) {
            int r0 = block_m + warp_m * WM + mt * 16 + (lane >> 2);
            int col = block_n + warp_n * 32 + nt * 8 + (lane & 3) * 2;
            if (r0 < M)
                *(__half2*)&C[(size_t)r0 * NOUT + col] = __floats2half2_rn(c[mt][nt][0], c[mt][nt][1]);
            int r1 = r0 + 8;
            if (r1 < M)
                *(__half2*)&C[(size_t)r1 * NOUT + col] = __floats2half2_rn(c[mt][nt][2], c[mt][nt][3]);
        }
    }
}

// ---------------------------------------------------------------------------
// helpers
// ---------------------------------------------------------------------------
__device__ __forceinline__ void h8_unpack(const uint4& u, float* f) {
    float2 p0 = __half22float2(*(const __half2*)&u.x);
    float2 p1 = __half22float2(*(const __half2*)&u.y);
    float2 p2 = __half22float2(*(const __half2*)&u.z);
    float2 p3 = __half22float2(*(const __half2*)&u.w);
    f[0] = p0.x; f[1] = p0.y; f[2] = p1.x; f[3] = p1.y;
    f[4] = p2.x; f[5] = p2.y; f[6] = p3.x; f[7] = p3.y;
}

// ---------------------------------------------------------------------------
// CSR gather D=256 (fp16 h): writes fp32 out AND fp16 copy (next GEMM input).
// ---------------------------------------------------------------------------
template <bool ACT>
__global__ void gather_csr_d256(const __half* __restrict__ h,
                                const float* __restrict__ b,
                                float* __restrict__ out,
                                __half* __restrict__ hcopy, int N) {
    int gw = (blockIdx.x * blockDim.x + threadIdx.x) >> 5;
    int lane = threadIdx.x & 31;
    if (gw >= N) return;

    float dd = g_dinv[gw];
    float w = dd * dd;

    float acc[8], f[8];
    {
        uint4 sv = ((const uint4*)(h + (size_t)gw * DH))[lane];
        h8_unpack(sv, f);
#pragma unroll
        for (int i = 0; i < 8; i++) acc[i] = w * f[i];
    }

    int e0 = g_row_off[gw];
    int e1 = g_row_off[gw + 1];
    int e = e0;
    for (; e + 1 < e1; e += 2) {
        int s0 = __ldg(&g_csr_src[e]);
        int s1 = __ldg(&g_csr_src[e + 1]);
        float n0 = g_dinv[s0] * dd;
        float n1 = g_dinv[s1] * dd;
        uint4 u0 = ((const uint4*)(h + (size_t)s0 * DH))[lane];
        uint4 u1 = ((const uint4*)(h + (size_t)s1 * DH))[lane];
        h8_unpack(u0, f);
#pragma unroll
        for (int i = 0; i < 8; i++) acc[i] = fmaf(n0, f[i], acc[i]);
        h8_unpack(u1, f);
#pragma unroll
        for (int i = 0; i < 8; i++) acc[i] = fmaf(n1, f[i], acc[i]);
    }
    if (e < e1) {
        int s0 = __ldg(&g_csr_src[e]);
        float n0 = g_dinv[s0] * dd;
        uint4 u0 = ((const uint4*)(h + (size_t)s0 * DH))[lane];
        h8_unpack(u0, f);
#pragma unroll
        for (int i = 0; i < 8; i++) acc[i] = fmaf(n0, f[i], acc[i]);
    }

    const float4* bb = (const float4*)b;
    float4 B0 = bb[lane * 2], B1 = bb[lane * 2 + 1];
    float o[8];
    o[0] = acc[0] + B0.x; o[1] = acc[1] + B0.y; o[2] = acc[2] + B0.z; o[3] = acc[3] + B0.w;
    o[4] = acc[4] + B1.x; o[5] = acc[5] + B1.y; o[6] = acc[6] + B1.z; o[7] = acc[7] + B1.w;
    if (ACT) {
#pragma unroll
        for (int i = 0; i < 8; i++) o[i] = o[i] > 0.f ? o[i] : SLOPE * o[i];
    }
    float4* op = (float4*)(out + (size_t)gw * DH);
    op[lane * 2]     = make_float4(o[0], o[1], o[2], o[3]);
    op[lane * 2 + 1] = make_float4(o[4], o[5], o[6], o[7]);
    __half2 h0 = __floats2half2_rn(o[0], o[1]);
    __half2 h1 = __floats2half2_rn(o[2], o[3]);
    __half2 h2 = __floats2half2_rn(o[4], o[5]);
    __half2 h3 = __floats2half2_rn(o[6], o[7]);
    uint4 pack = make_uint4(*(uint32_t*)&h0, *(uint32_t*)&h1, *(uint32_t*)&h2, *(uint32_t*)&h3);
    ((uint4*)(hcopy + (size_t)gw * DH))[lane] = pack;
}

// ---------------------------------------------------------------------------
// CSR gather D=64 (fp16 h): half-warps split even/odd edges, shfl-combine.
// ---------------------------------------------------------------------------
template <bool ACT>
__global__ void gather_csr_d64(const __half* __restrict__ h,
                               const float* __restrict__ b,
                               float* __restrict__ out, int N) {
    int gw = (blockIdx.x * blockDim.x + threadIdx.x) >> 5;
    int lane = threadIdx.x & 31;
    int l16 = lane & 15;
    int half = lane >> 4;
    if (gw >= N) return;

    float dd = g_dinv[gw];
    int e0 = g_row_off[gw];
    int e1 = g_row_off[gw + 1];

    float acc[4] = {0.f, 0.f, 0.f, 0.f};
    for (int e = e0 + half; e < e1; e += 2) {
        int s = __ldg(&g_csr_src[e]);
        float norm = g_dinv[s] * dd;
        uint2 u = ((const uint2*)(h + (size_t)s * DOUT))[l16];
        float2 p0 = __half22float2(*(const __half2*)&u.x);
        float2 p1 = __half22float2(*(const __half2*)&u.y);
        acc[0] = fmaf(norm, p0.x, acc[0]);
        acc[1] = fmaf(norm, p0.y, acc[1]);
        acc[2] = fmaf(norm, p1.x, acc[2]);
        acc[3] = fmaf(norm, p1.y, acc[3]);
    }
#pragma unroll
    for (int i = 0; i < 4; i++)
        acc[i] += __shfl_xor_sync(0xffffffffu, acc[i], 16);

    if (half == 0) {
        float w = dd * dd;
        uint2 u = ((const uint2*)(h + (size_t)gw * DOUT))[l16];
        float2 p0 = __half22float2(*(const __half2*)&u.x);
        float2 p1 = __half22float2(*(const __half2*)&u.y);
        float4 B = ((const float4*)b)[l16];
        float4 o;
        o.x = fmaf(w, p0.x, acc[0]) + B.x;
        o.y = fmaf(w, p0.y, acc[1]) + B.y;
        o.z = fmaf(w, p1.x, acc[2]) + B.z;
        o.w = fmaf(w, p1.y, acc[3]) + B.w;
        if (ACT) {
            o.x = o.x > 0.f ? o.x : SLOPE * o.x;
            o.y = o.y > 0.f ? o.y : SLOPE * o.y;
            o.z = o.z > 0.f ? o.z : SLOPE * o.z;
            o.w = o.w > 0.f ? o.w : SLOPE * o.w;
        }
        ((float4*)(out + (size_t)gw * DOUT))[l16] = o;
    }
}

// ---------------------------------------------------------------------------
// launch — CSR build forked onto a second stream, joined before gather-1.
// Stream/event handles are host-side only (created+destroyed per call; the
// captured graph keeps only the dependency edges, nothing host-side is timed).
// ---------------------------------------------------------------------------
extern "C" void kernel_launch(void* const* d_in, const int* in_sizes, int n_in,
                              void* d_out, int out_size) {
    const float* x  = (const float*)d_in[0];
    const int*   ei = (const int*)d_in[1];
    const float* W1 = (const float*)d_in[2];
    const float* b1 = (const float*)d_in[3];
    const float* W2 = (const float*)d_in[4];
    const float* b2 = (const float*)d_in[5];
    const float* W3 = (const float*)d_in[6];
    const float* b3 = (const float*)d_in[7];
    float* out = (float*)d_out;

    const int N = in_sizes[0] / DH;
    const int E = in_sizes[1] / 2;
    const int* src = ei;
    const int* dstp = ei + E;

    float* h1 = out;
    float* h2 = out + (size_t)N * DH;
    float* lg = out + 2 * (size_t)N * DH;

    __half *hbuf, *a16, *w1h, *w2h, *w3h;
    cudaGetSymbolAddress((void**)&hbuf, g_h);
    cudaGetSymbolAddress((void**)&a16, g_a16);
    cudaGetSymbolAddress((void**)&w1h, g_w1);
    cudaGetSymbolAddress((void**)&w2h, g_w2);
    cudaGetSymbolAddress((void**)&w3h, g_w3);
    int* degp = nullptr;
    cudaGetSymbolAddress((void**)&degp, g_deg);

    const int SMEM128 = 2 * (128 * 40 * 2 + 128 * 40 * 2);  // 40960
    const int SMEM64  = 2 * (128 * 40 * 2 + 64 * 40 * 2);   // 30720
    cudaFuncSetAttribute(gemm_f16<128>, cudaFuncAttributeMaxDynamicSharedMemorySize, SMEM128);
    cudaFuncSetAttribute(gemm_f16<64>,  cudaFuncAttributeMaxDynamicSharedMemorySize, SMEM64);

    const int NB = (N + 255) / 256;
    const int gather_blocks = (N + 7) / 8;
    const int tiles_m = (N + 127) / 128;

    // fork: CSR build + W2/W3 conversion on side stream
    cudaStream_t sB;
    cudaStreamCreate(&sB);
    cudaEvent_t eFork, eJoin;
    cudaEventCreateWithFlags(&eFork, cudaEventDisableTiming);
    cudaEventCreateWithFlags(&eJoin, cudaEventDisableTiming);

    cudaEventRecord(eFork, 0);
    cudaStreamWaitEvent(sB, eFork, 0);

    // --- branch B (side stream): degree / dinv / CSR + W2/W3 fp16 prep ---
    cudaMemsetAsync(degp, 0, N * sizeof(int), sB);
    count_deg_kernel<<<(E + 255) / 256, 256, 0, sB>>>(dstp, E);
    offsets_lookback_kernel<<<NB, 256, 0, sB>>>(N, E);
    fill_csr_kernel<<<(E + 255) / 256, 256, 0, sB>>>(src, dstp, E);
    f2h_kernel<<<(DH * DH / 4 + 255) / 256, 256, 0, sB>>>(W2, w2h, DH * DH / 4);
    f2h_kernel<<<(DOUT * DH / 4 + 255) / 256, 256, 0, sB>>>(W3, w3h, DOUT * DH / 4);
    cudaEventRecord(eJoin, sB);

    // --- branch A (main stream): x/W1 fp16 prep + layer-1 GEMM ---
    f2h_kernel<<<(N * (DH / 4) + 255) / 256, 256>>>(x, a16, N * (DH / 4));
    f2h_kernel<<<(DH * DH / 4 + 255) / 256, 256>>>(W1, w1h, DH * DH / 4);
    gemm_f16<128><<<dim3(tiles_m, DH / 128), 256, SMEM128>>>(a16, w1h, hbuf, N, DH);

    // join: gather-1 needs the CSR
    cudaStreamWaitEvent(0, eJoin, 0);
    gather_csr_d256<true><<<gather_blocks, 256>>>(hbuf, b1, h1, a16, N);

    // --- layer 2 ---
    gemm_f16<128><<<dim3(tiles_m, DH / 128), 256, SMEM128>>>(a16, w2h, hbuf, N, DH);
    gather_csr_d256<true><<<gather_blocks, 256>>>(hbuf, b2, h2, a16, N);

    // --- layer 3 ---
    gemm_f16<64><<<dim3(tiles_m, DOUT / 64), 256, SMEM64>>>(a16, w3h, hbuf, N, DOUT);
    gather_csr_d64<false><<<gather_blocks, 256>>>(hbuf, b3, lg, N);

    cudaEventDestroy(eFork);
    cudaEventDestroy(eJoin);
    cudaStreamDestroy(sB);
}